// round 14
// baseline (speedup 1.0000x reference)
#include <cuda_runtime.h>
#include <cuda_fp16.h>
#include <cstdint>

#define RES    300
#define NCOMP  48
#define PCH    64
#define NFEAT  27
#define KTOT   144
#define NPTS_BLK 192
#define THREADS  384

#define FROWB  304
#define F_OFF    0
#define F_BYTES  (NPTS_BLK * FROWB)         // 58368
#define WH_OFF   F_BYTES
#define WHROWB 336
#define WH_BYTES (32 * WHROWB)              // 10752
#define XYZ_OFF  (WH_OFF + WH_BYTES)        // 69120
#define XYZ_BYTES (NPTS_BLK * 3 * 4)        // 2304
#define SMEM_DYN (XYZ_OFF + XYZ_BYTES)      // 71424
#define OSTRIDE  120

// Scratch: channel-last transposed fp16 copies, 64-ch padded rows.
__device__ __align__(128) __half g_planesH[3u * RES * RES * PCH];
__device__ __align__(128) __half g_linesH [3u * RES * PCH];

// ---------------------------------------------------------------------------
__global__ void transpose_planes_kernel(const float* __restrict__ planes) {
    __shared__ float tile[NCOMP][33];
    const int i  = blockIdx.z;
    const int y  = blockIdx.y;
    const int xt = blockIdx.x * 32;
    const int t  = threadIdx.x;
    const int tx = t & 31;
    const int tc = t >> 5;
    const int x  = xt + tx;
    #pragma unroll
    for (int r = 0; r < 6; r++) {
        const int c = tc + 8 * r;
        if (x < RES)
            tile[c][tx] = planes[(((size_t)i * NCOMP + c) * RES + y) * RES + x];
    }
    __syncthreads();
    const int nx = min(32, RES - xt);
    __half* outb = g_planesH + (((size_t)i * RES + y) * RES + xt) * PCH;
    for (int e = t; e < nx * NCOMP; e += 256) {
        const int xl = e / NCOMP;
        const int c  = e - xl * NCOMP;
        outb[(size_t)xl * PCH + c] = __float2half(tile[c][xl]);
    }
}

__global__ void transpose_lines_kernel(const float* __restrict__ lines) {
    const int e = blockIdx.x * 256 + threadIdx.x;
    if (e >= 3 * RES * NCOMP) return;
    const int c  = e % NCOMP;
    const int ir = e / NCOMP;
    const int r  = ir % RES;
    const int i  = ir / RES;
    g_linesH[(size_t)ir * PCH + c] = __float2half(lines[((size_t)i * NCOMP + c) * RES + r]);
}

// ---------------------------------------------------------------------------
__device__ __forceinline__ uint32_t smem_u32(const void* p) {
    uint32_t a;
    asm("{ .reg .u64 t; cvta.to.shared.u64 t, %1; cvt.u32.u64 %0, t; }"
        : "=r"(a) : "l"(p));
    return a;
}
__device__ __forceinline__ __half2 uh2(uint32_t u) {
    return *reinterpret_cast<const __half2*>(&u);
}
__device__ __forceinline__ uint32_t h2u(__half2 h) {
    return *reinterpret_cast<const uint32_t*>(&h);
}
__device__ __forceinline__ void ldsm_x4(uint32_t& r0, uint32_t& r1,
                                        uint32_t& r2, uint32_t& r3, uint32_t addr) {
    asm volatile("ldmatrix.sync.aligned.m8n8.x4.shared.b16 {%0,%1,%2,%3}, [%4];"
                 : "=r"(r0), "=r"(r1), "=r"(r2), "=r"(r3) : "r"(addr));
}
__device__ __forceinline__ void mma16816(float* c,
                                         uint32_t a0, uint32_t a1, uint32_t a2, uint32_t a3,
                                         uint32_t b0, uint32_t b1) {
    asm volatile("mma.sync.aligned.m16n8k16.row.col.f32.f16.f16.f32 "
                 "{%0,%1,%2,%3}, {%4,%5,%6,%7}, {%8,%9}, {%0,%1,%2,%3};"
                 : "+f"(c[0]), "+f"(c[1]), "+f"(c[2]), "+f"(c[3])
                 : "r"(a0), "r"(a1), "r"(a2), "r"(a3), "r"(b0), "r"(b1));
}

// Per-step coordinate helper (step j = it*3 + plane i)
struct StepCoord {
    float wx, wy, wz;
    const __half *t00, *t01, *t10, *t11, *l0, *l1;
    int p, co;
};

__device__ __forceinline__ StepCoord step_coord(int j, int tid, const float* sXYZ) {
    StepCoord sc;
    const int it  = j / 3;
    const int i   = j - it * 3;
    const int s   = tid + it * THREADS;
    sc.p  = s / 6;
    const int c16 = s - sc.p * 6;
    sc.co = c16 * 8;

    const float p0 = sXYZ[sc.p * 3 + 0];
    const float p1 = sXYZ[sc.p * 3 + 1];
    const float p2 = sXYZ[sc.p * 3 + 2];
    const float gx = (i == 2) ? p1 : p2;
    const float gy = (i == 0) ? p1 : p0;
    const float gz = (i == 0) ? p0 : ((i == 1) ? p1 : p2);

    const float k = 0.5f * (float)(RES - 1);
    const float x = (gx + 1.0f) * k, y = (gy + 1.0f) * k, z = (gz + 1.0f) * k;
    const float xf = floorf(x), yf = floorf(y), zf = floorf(z);
    sc.wx = x - xf; sc.wy = y - yf; sc.wz = z - zf;
    const int x0 = min(max((int)xf, 0), RES - 1); const int x1 = min(x0 + 1, RES - 1);
    const int y0 = min(max((int)yf, 0), RES - 1); const int y1 = min(y0 + 1, RES - 1);
    const int z0 = min(max((int)zf, 0), RES - 1); const int z1 = min(z0 + 1, RES - 1);

    const __half* P = g_planesH + (size_t)i * (RES * RES * PCH);
    const __half* L = g_linesH  + (size_t)i * (RES * PCH);
    sc.t00 = P + ((size_t)y0 * RES + x0) * PCH + sc.co;
    sc.t01 = P + ((size_t)y0 * RES + x1) * PCH + sc.co;
    sc.t10 = P + ((size_t)y1 * RES + x0) * PCH + sc.co;
    sc.t11 = P + ((size_t)y1 * RES + x1) * PCH + sc.co;
    sc.l0  = L + (size_t)z0 * PCH + sc.co;
    sc.l1  = L + (size_t)z1 * PCH + sc.co;
    return sc;
}

// ---------------------------------------------------------------------------
// Main: phase1 = depth-1 software-pipelined gather (12 loads in flight) +
//       HFMA2 interp; phase2 = HMMA matvec. 2 CTAs/SM, ~80 regs.
// ---------------------------------------------------------------------------
__global__ __launch_bounds__(THREADS, 2)
void tvm_main_kernel(const float* __restrict__ xyz,
                     const float* __restrict__ basisW,
                     float* __restrict__ out,
                     int npts) {
    extern __shared__ char sm[];
    float* sXYZ = reinterpret_cast<float*>(sm + XYZ_OFF);
    const uint32_t sbase = smem_u32(sm);

    const int tid  = threadIdx.x;
    const int base = blockIdx.x * NPTS_BLK;

    for (int e = tid; e < WH_BYTES / 16; e += THREADS)
        *reinterpret_cast<uint4*>(sm + WH_OFF + e * 16) = make_uint4(0, 0, 0, 0);
    __syncthreads();
    for (int e = tid; e < NFEAT * KTOT; e += THREADS) {
        const int n = e / KTOT;
        const int k = e - n * KTOT;
        *reinterpret_cast<__half*>(sm + WH_OFF + n * WHROWB + k * 2) =
            __float2half(basisW[e]);
    }
    for (int e = tid; e < NPTS_BLK * 3; e += THREADS) {
        const int p = e / 3;
        const int c = e - p * 3;
        sXYZ[e] = xyz[(size_t)min(base + p, npts - 1) * 3 + c];
    }
    __syncthreads();

    // ---------------- Phase 1: pipelined gather + fp16 interp ----------------
    {
        StepCoord sc = step_coord(0, tid, sXYZ);
        uint4 c00 = *(const uint4*)sc.t00;
        uint4 c01 = *(const uint4*)sc.t01;
        uint4 c10 = *(const uint4*)sc.t10;
        uint4 c11 = *(const uint4*)sc.t11;
        uint4 cl0 = *(const uint4*)sc.l0;
        uint4 cl1 = *(const uint4*)sc.l1;

        #pragma unroll
        for (int j = 0; j < 9; j++) {
            // prefetch next step's 6 taps
            StepCoord nsc;
            uint4 n00, n01, n10, n11, nl0, nl1;
            if (j < 8) {
                nsc = step_coord(j + 1, tid, sXYZ);
                n00 = *(const uint4*)nsc.t00;
                n01 = *(const uint4*)nsc.t01;
                n10 = *(const uint4*)nsc.t10;
                n11 = *(const uint4*)nsc.t11;
                nl0 = *(const uint4*)nsc.l0;
                nl1 = *(const uint4*)nsc.l1;
            }

            // interp current step (all HFMA2)
            const __half2 w00h = __float2half2_rn((1.0f - sc.wx) * (1.0f - sc.wy));
            const __half2 w01h = __float2half2_rn(sc.wx * (1.0f - sc.wy));
            const __half2 w10h = __float2half2_rn((1.0f - sc.wx) * sc.wy);
            const __half2 w11h = __float2half2_rn(sc.wx * sc.wy);
            const __half2 lw0h = __float2half2_rn(1.0f - sc.wz);
            const __half2 lw1h = __float2half2_rn(sc.wz);

            const uint32_t* a00 = &c00.x; const uint32_t* a01 = &c01.x;
            const uint32_t* a10 = &c10.x; const uint32_t* a11 = &c11.x;
            const uint32_t* aL0 = &cl0.x; const uint32_t* aL1 = &cl1.x;
            uint32_t fw[4];
            #pragma unroll
            for (int w = 0; w < 4; w++) {
                __half2 pf = __hmul2(w00h, uh2(a00[w]));
                pf = __hfma2(w01h, uh2(a01[w]), pf);
                pf = __hfma2(w10h, uh2(a10[w]), pf);
                pf = __hfma2(w11h, uh2(a11[w]), pf);
                __half2 lf = __hmul2(lw0h, uh2(aL0[w]));
                lf = __hfma2(lw1h, uh2(aL1[w]), lf);
                fw[w] = h2u(__hmul2(pf, lf));
            }
            const int i = j - (j / 3) * 3;
            *reinterpret_cast<uint4*>(sm + F_OFF + (size_t)sc.p * FROWB
                                      + (i * NCOMP + sc.co) * 2) =
                make_uint4(fw[0], fw[1], fw[2], fw[3]);

            if (j < 8) {
                sc = nsc;
                c00 = n00; c01 = n01; c10 = n10; c11 = n11; cl0 = nl0; cl1 = nl1;
            }
        }
    }
    __syncthreads();

    // ---------------- Phase 2: HMMA matvec ----------------
    const int wid  = tid >> 5;
    const int lane = tid & 31;
    const int l16  = lane & 15;
    const int g    = lane >> 3;

    const uint32_t a_addr = sbase + F_OFF
        + (uint32_t)(16 * wid + l16) * FROWB + (uint32_t)(lane >> 4) * 16;
    const uint32_t b_addr = sbase + WH_OFF
        + (uint32_t)((g & 2) * 4 + (lane & 7)) * WHROWB + (uint32_t)(g & 1) * 16;

    float c[4][4];
    #pragma unroll
    for (int nt = 0; nt < 4; nt++)
        #pragma unroll
        for (int q = 0; q < 4; q++) c[nt][q] = 0.0f;

    #pragma unroll
    for (int ks = 0; ks < 9; ks++) {
        uint32_t a0, a1, a2, a3;
        ldsm_x4(a0, a1, a2, a3, a_addr + ks * 32);
        #pragma unroll
        for (int ntp = 0; ntp < 2; ntp++) {
            uint32_t b0, b1, b2, b3;
            ldsm_x4(b0, b1, b2, b3, b_addr + (uint32_t)ntp * (16 * WHROWB) + ks * 32);
            mma16816(c[2 * ntp],     a0, a1, a2, a3, b0, b1);
            mma16816(c[2 * ntp + 1], a0, a1, a2, a3, b2, b3);
        }
    }
    __syncthreads();

    // Epilogue: stage D rows at OSTRIDE-padded rows.
    {
        const int gq = lane >> 2;
        const int t  = lane & 3;
        char* stg = sm + F_OFF;
        #pragma unroll
        for (int nt = 0; nt < 4; nt++) {
            const int j0 = nt * 8 + 2 * t;
            if (j0 < 30) {
                *reinterpret_cast<float2*>(stg + (size_t)(16 * wid + gq) * OSTRIDE + j0 * 4) =
                    make_float2(c[nt][0], c[nt][1]);
                *reinterpret_cast<float2*>(stg + (size_t)(16 * wid + gq + 8) * OSTRIDE + j0 * 4) =
                    make_float2(c[nt][2], c[nt][3]);
            }
        }
    }
    __syncthreads();

    // coalesced store
    for (int e = tid; e < NPTS_BLK * NFEAT; e += THREADS) {
        const int pt = e / NFEAT;
        const int j  = e - pt * NFEAT;
        if (base + pt < npts)
            out[(size_t)(base + pt) * NFEAT + j] =
                *reinterpret_cast<const float*>(sm + F_OFF + (size_t)pt * OSTRIDE + j * 4);
    }
}

// ---------------------------------------------------------------------------
extern "C" void kernel_launch(void* const* d_in, const int* in_sizes, int n_in,
                              void* d_out, int out_size) {
    const float* xyz    = (const float*)d_in[0];
    const float* planes = (const float*)d_in[1];
    const float* lines  = (const float*)d_in[2];
    const float* basisW = (const float*)d_in[3];
    float* out = (float*)d_out;
    const int npts = in_sizes[0] / 3;

    cudaFuncSetAttribute(tvm_main_kernel,
                         cudaFuncAttributeMaxDynamicSharedMemorySize, SMEM_DYN);

    dim3 tg((RES + 31) / 32, RES, 3);
    transpose_planes_kernel<<<tg, 256>>>(planes);
    transpose_lines_kernel<<<(3 * RES * NCOMP + 255) / 256, 256>>>(lines);
    const int nblk = (npts + NPTS_BLK - 1) / NPTS_BLK;
    tvm_main_kernel<<<nblk, THREADS, SMEM_DYN>>>(xyz, basisW, out, npts);
}

// round 15
// speedup vs baseline: 1.0910x; 1.0910x over previous
#include <cuda_runtime.h>
#include <cuda_fp16.h>
#include <cstdint>

#define RES    300
#define NCOMP  48
#define PCH    64                           // padded channel stride (128B rows)
#define NFEAT  27
#define KTOT   144
#define NPTS_BLK 192
#define THREADS  384

#define FROWB  304
#define F_OFF    0
#define F_BYTES  (NPTS_BLK * FROWB)         // 58368
#define WH_OFF   F_BYTES
#define WHROWB 336
#define WH_BYTES (32 * WHROWB)              // 10752
#define XYZ_OFF  (WH_OFF + WH_BYTES)        // 69120
#define XYZ_BYTES (NPTS_BLK * 3 * 4)        // 2304
#define SMEM_DYN (XYZ_OFF + XYZ_BYTES)      // 71424 -> 3 CTAs/SM
#define OSTRIDE  120

// Scratch: channel-last transposed fp16 copies, 64-ch padded rows.
__device__ __align__(128) __half g_planesH[3u * RES * RES * PCH];
__device__ __align__(128) __half g_linesH [3u * RES * PCH];

// ---------------------------------------------------------------------------
__global__ void transpose_planes_kernel(const float* __restrict__ planes) {
    __shared__ float tile[NCOMP][33];
    const int i  = blockIdx.z;
    const int y  = blockIdx.y;
    const int xt = blockIdx.x * 32;
    const int t  = threadIdx.x;
    const int tx = t & 31;
    const int tc = t >> 5;
    const int x  = xt + tx;
    #pragma unroll
    for (int r = 0; r < 6; r++) {
        const int c = tc + 8 * r;
        if (x < RES)
            tile[c][tx] = planes[(((size_t)i * NCOMP + c) * RES + y) * RES + x];
    }
    __syncthreads();
    const int nx = min(32, RES - xt);
    __half* outb = g_planesH + (((size_t)i * RES + y) * RES + xt) * PCH;
    for (int e = t; e < nx * NCOMP; e += 256) {
        const int xl = e / NCOMP;
        const int c  = e - xl * NCOMP;
        outb[(size_t)xl * PCH + c] = __float2half(tile[c][xl]);
    }
}

__global__ void transpose_lines_kernel(const float* __restrict__ lines) {
    const int e = blockIdx.x * 256 + threadIdx.x;
    if (e >= 3 * RES * NCOMP) return;
    const int c  = e % NCOMP;
    const int ir = e / NCOMP;
    const int r  = ir % RES;
    const int i  = ir / RES;
    g_linesH[(size_t)ir * PCH + c] = __float2half(lines[((size_t)i * NCOMP + c) * RES + r]);
}

// ---------------------------------------------------------------------------
__device__ __forceinline__ uint32_t smem_u32(const void* p) {
    uint32_t a;
    asm("{ .reg .u64 t; cvta.to.shared.u64 t, %1; cvt.u32.u64 %0, t; }"
        : "=r"(a) : "l"(p));
    return a;
}
__device__ __forceinline__ __half2 uh2(uint32_t u) {
    return *reinterpret_cast<const __half2*>(&u);
}
__device__ __forceinline__ uint32_t h2u(__half2 h) {
    return *reinterpret_cast<const uint32_t*>(&h);
}
__device__ __forceinline__ void ldsm_x4(uint32_t& r0, uint32_t& r1,
                                        uint32_t& r2, uint32_t& r3, uint32_t addr) {
    asm volatile("ldmatrix.sync.aligned.m8n8.x4.shared.b16 {%0,%1,%2,%3}, [%4];"
                 : "=r"(r0), "=r"(r1), "=r"(r2), "=r"(r3) : "r"(addr));
}
__device__ __forceinline__ void mma16816(float* c,
                                         uint32_t a0, uint32_t a1, uint32_t a2, uint32_t a3,
                                         uint32_t b0, uint32_t b1) {
    asm volatile("mma.sync.aligned.m16n8k16.row.col.f32.f16.f16.f32 "
                 "{%0,%1,%2,%3}, {%4,%5,%6,%7}, {%8,%9}, {%0,%1,%2,%3};"
                 : "+f"(c[0]), "+f"(c[1]), "+f"(c[2]), "+f"(c[3])
                 : "r"(a0), "r"(a1), "r"(a2), "r"(a3), "r"(b0), "r"(b1));
}

// ---------------------------------------------------------------------------
// Main: phase1 = 6-lane cooperative gather + HFMA2 interp, plane loop fully
//       unrolled (ptxas batches loads across planes up to the 56-reg cap);
//       phase2 = HMMA matvec.
// ---------------------------------------------------------------------------
__global__ __launch_bounds__(THREADS, 3)
void tvm_main_kernel(const float* __restrict__ xyz,
                     const float* __restrict__ basisW,
                     float* __restrict__ out,
                     int npts) {
    extern __shared__ char sm[];
    float* sXYZ = reinterpret_cast<float*>(sm + XYZ_OFF);
    const uint32_t sbase = smem_u32(sm);

    const int tid  = threadIdx.x;
    const int base = blockIdx.x * NPTS_BLK;

    // Stage W as fp16 [n=0..31][k=0..143], rows 27-31 zero.
    for (int e = tid; e < WH_BYTES / 16; e += THREADS)
        *reinterpret_cast<uint4*>(sm + WH_OFF + e * 16) = make_uint4(0, 0, 0, 0);
    __syncthreads();
    for (int e = tid; e < NFEAT * KTOT; e += THREADS) {
        const int n = e / KTOT;
        const int k = e - n * KTOT;
        *reinterpret_cast<__half*>(sm + WH_OFF + n * WHROWB + k * 2) =
            __float2half(basisW[e]);
    }
    for (int e = tid; e < NPTS_BLK * 3; e += THREADS) {
        const int p = e / 3;
        const int c = e - p * 3;
        sXYZ[e] = xyz[(size_t)min(base + p, npts - 1) * 3 + c];
    }
    __syncthreads();

    // ---------------- Phase 1: gather + fp16 interp ----------------
    #pragma unroll 1
    for (int it = 0; it < 3; it++) {
        const int s   = tid + it * THREADS;
        const int p   = s / 6;
        const int c16 = s - p * 6;
        const int co  = c16 * 8;

        const float p0 = sXYZ[p * 3 + 0];
        const float p1 = sXYZ[p * 3 + 1];
        const float p2 = sXYZ[p * 3 + 2];

        #pragma unroll
        for (int i = 0; i < 3; i++) {      // FULL unroll: cross-plane load batching
            const float gx = (i == 2) ? p1 : p2;
            const float gy = (i == 0) ? p1 : p0;
            const float gz = (i == 0) ? p0 : ((i == 1) ? p1 : p2);

            const float sc = 0.5f * (float)(RES - 1);
            const float x = (gx + 1.0f) * sc, y = (gy + 1.0f) * sc, z = (gz + 1.0f) * sc;
            const float xf = floorf(x), yf = floorf(y), zf = floorf(z);
            const float wx = x - xf, wy = y - yf, wz = z - zf;
            const int x0 = min(max((int)xf, 0), RES - 1); const int x1 = min(x0 + 1, RES - 1);
            const int y0 = min(max((int)yf, 0), RES - 1); const int y1 = min(y0 + 1, RES - 1);
            const int z0 = min(max((int)zf, 0), RES - 1); const int z1 = min(z0 + 1, RES - 1);

            const __half2 w00h = __float2half2_rn((1.0f - wx) * (1.0f - wy));
            const __half2 w01h = __float2half2_rn(wx * (1.0f - wy));
            const __half2 w10h = __float2half2_rn((1.0f - wx) * wy);
            const __half2 w11h = __float2half2_rn(wx * wy);
            const __half2 lw0h = __float2half2_rn(1.0f - wz);
            const __half2 lw1h = __float2half2_rn(wz);

            const __half* P = g_planesH + (size_t)i * (RES * RES * PCH);
            const __half* L = g_linesH  + (size_t)i * (RES * PCH);
            const uint4 t00 = *(const uint4*)(P + ((size_t)y0 * RES + x0) * PCH + co);
            const uint4 t01 = *(const uint4*)(P + ((size_t)y0 * RES + x1) * PCH + co);
            const uint4 t10 = *(const uint4*)(P + ((size_t)y1 * RES + x0) * PCH + co);
            const uint4 t11 = *(const uint4*)(P + ((size_t)y1 * RES + x1) * PCH + co);
            const uint4 tL0 = *(const uint4*)(L + (size_t)z0 * PCH + co);
            const uint4 tL1 = *(const uint4*)(L + (size_t)z1 * PCH + co);

            const uint32_t* a00 = &t00.x; const uint32_t* a01 = &t01.x;
            const uint32_t* a10 = &t10.x; const uint32_t* a11 = &t11.x;
            const uint32_t* aL0 = &tL0.x; const uint32_t* aL1 = &tL1.x;
            uint32_t fw[4];
            #pragma unroll
            for (int w = 0; w < 4; w++) {
                __half2 pf = __hmul2(w00h, uh2(a00[w]));
                pf = __hfma2(w01h, uh2(a01[w]), pf);
                pf = __hfma2(w10h, uh2(a10[w]), pf);
                pf = __hfma2(w11h, uh2(a11[w]), pf);
                __half2 lf = __hmul2(lw0h, uh2(aL0[w]));
                lf = __hfma2(lw1h, uh2(aL1[w]), lf);
                fw[w] = h2u(__hmul2(pf, lf));
            }
            *reinterpret_cast<uint4*>(sm + F_OFF + (size_t)p * FROWB + (i * NCOMP + co) * 2) =
                make_uint4(fw[0], fw[1], fw[2], fw[3]);
        }
    }
    __syncthreads();

    // ---------------- Phase 2: HMMA matvec ----------------
    const int wid  = tid >> 5;
    const int lane = tid & 31;
    const int l16  = lane & 15;
    const int g    = lane >> 3;

    const uint32_t a_addr = sbase + F_OFF
        + (uint32_t)(16 * wid + l16) * FROWB + (uint32_t)(lane >> 4) * 16;
    const uint32_t b_addr = sbase + WH_OFF
        + (uint32_t)((g & 2) * 4 + (lane & 7)) * WHROWB + (uint32_t)(g & 1) * 16;

    float c[4][4];
    #pragma unroll
    for (int nt = 0; nt < 4; nt++)
        #pragma unroll
        for (int q = 0; q < 4; q++) c[nt][q] = 0.0f;

    #pragma unroll
    for (int ks = 0; ks < 9; ks++) {
        uint32_t a0, a1, a2, a3;
        ldsm_x4(a0, a1, a2, a3, a_addr + ks * 32);
        #pragma unroll
        for (int ntp = 0; ntp < 2; ntp++) {
            uint32_t b0, b1, b2, b3;
            ldsm_x4(b0, b1, b2, b3, b_addr + (uint32_t)ntp * (16 * WHROWB) + ks * 32);
            mma16816(c[2 * ntp],     a0, a1, a2, a3, b0, b1);
            mma16816(c[2 * ntp + 1], a0, a1, a2, a3, b2, b3);
        }
    }
    __syncthreads();

    // Epilogue: stage D rows at OSTRIDE-padded rows.
    {
        const int gq = lane >> 2;
        const int t  = lane & 3;
        char* stg = sm + F_OFF;
        #pragma unroll
        for (int nt = 0; nt < 4; nt++) {
            const int j0 = nt * 8 + 2 * t;
            if (j0 < 30) {
                *reinterpret_cast<float2*>(stg + (size_t)(16 * wid + gq) * OSTRIDE + j0 * 4) =
                    make_float2(c[nt][0], c[nt][1]);
                *reinterpret_cast<float2*>(stg + (size_t)(16 * wid + gq + 8) * OSTRIDE + j0 * 4) =
                    make_float2(c[nt][2], c[nt][3]);
            }
        }
    }
    __syncthreads();

    // coalesced store
    for (int e = tid; e < NPTS_BLK * NFEAT; e += THREADS) {
        const int pt = e / NFEAT;
        const int j  = e - pt * NFEAT;
        if (base + pt < npts)
            out[(size_t)(base + pt) * NFEAT + j] =
                *reinterpret_cast<const float*>(sm + F_OFF + (size_t)pt * OSTRIDE + j * 4);
    }
}

// ---------------------------------------------------------------------------
extern "C" void kernel_launch(void* const* d_in, const int* in_sizes, int n_in,
                              void* d_out, int out_size) {
    const float* xyz    = (const float*)d_in[0];
    const float* planes = (const float*)d_in[1];
    const float* lines  = (const float*)d_in[2];
    const float* basisW = (const float*)d_in[3];
    float* out = (float*)d_out;
    const int npts = in_sizes[0] / 3;

    cudaFuncSetAttribute(tvm_main_kernel,
                         cudaFuncAttributeMaxDynamicSharedMemorySize, SMEM_DYN);

    dim3 tg((RES + 31) / 32, RES, 3);
    transpose_planes_kernel<<<tg, 256>>>(planes);
    transpose_lines_kernel<<<(3 * RES * NCOMP + 255) / 256, 256>>>(lines);
    const int nblk = (npts + NPTS_BLK - 1) / NPTS_BLK;
    tvm_main_kernel<<<nblk, THREADS, SMEM_DYN>>>(xyz, basisW, out, npts);
}